// round 5
// baseline (speedup 1.0000x reference)
#include <cuda_runtime.h>
#include <stdint.h>

#define N_FFT  4096
#define NBINS  2049
#define NMICS  8
#define BATCH  16
#define NPAIR  28
#define NLAG   81
#define SRP_BLOCKS 148
#define SRP_THREADS 1024

// padded smem index for FFT: conflict-free for all access patterns used here
#define SP(i) ((i) + ((i) >> 4) + ((i) >> 8))
#define SMEM_PAD 4368

__device__ float2 g_W[BATCH * NMICS * NBINS];        // whitened spectra (natural order)
__device__ float  g_cc[NPAIR * NLAG * BATCH];        // cc table [p][t][b16]
__device__ unsigned long long g_best[BATCH];
__device__ int    g_done;
__device__ float2 g_tw3[1360 * 3];                   // stage twiddles (W,W^2,W^3)

// base-4 digit reversal of 12-bit index (involution)
__device__ __forceinline__ int dr12(int i)
{
    unsigned x = __brev((unsigned)i) >> 20;
    return (int)(((x & 0xAAAu) >> 1) | ((x & 0x555u) << 1));
}

__device__ __forceinline__ float2 cmul(float2 a, float2 b)
{
    return make_float2(a.x * b.x - a.y * b.y, a.x * b.y + a.y * b.x);
}

// ---------------------------------------------------------------------------
// init: twiddle tables + reset argmax state.
// ---------------------------------------------------------------------------
__global__ void k_init()
{
    int gid = blockIdx.x * 256 + threadIdx.x;
    if (gid == 0) {
        g_done = 0;
        #pragma unroll
        for (int b = 0; b < BATCH; ++b) g_best[b] = 0ull;
    }
    if (gid < 1360) {
        int Q, k;
        if      (gid < 1024) { Q = 1024; k = gid; }
        else if (gid < 1280) { Q = 256;  k = gid - 1024; }
        else if (gid < 1344) { Q = 64;   k = gid - 1280; }
        else                 { Q = 16;   k = gid - 1344; }
        float th = -3.14159265358979323846f * (float)k / (2.0f * (float)Q);
        #pragma unroll
        for (int m = 1; m <= 3; ++m) {
            float sn, cs;
            sincosf(th * (float)m, &sn, &cs);
            g_tw3[gid * 3 + (m - 1)] = make_float2(cs, sn);
        }
    }
}

// ---------------------------------------------------------------------------
// In-place 4096-pt radix-4 DIF FFT (padded smem). Natural input, digit-
// reversed output. 4 table stages + in-register radix-16 tail.
// ---------------------------------------------------------------------------
template<int DIR>
__device__ __forceinline__ void fft4096_dif(float2* s, int tid)
{
    const float sg = (DIR < 0) ? 1.0f : -1.0f;

    const int OFF[4] = {0, 1024, 1280, 1344};
    #pragma unroll
    for (int st = 0; st < 4; ++st) {
        const int lg = 10 - 2 * st;
        const int Q  = 1 << lg;
        #pragma unroll
        for (int u = 0; u < 4; ++u) {
            int j    = tid + u * 256;
            int k    = j & (Q - 1);
            int base = ((j >> lg) << (lg + 2)) + k;

            float2 a0 = s[SP(base)];
            float2 a1 = s[SP(base + Q)];
            float2 a2 = s[SP(base + 2 * Q)];
            float2 a3 = s[SP(base + 3 * Q)];

            float2 A = make_float2(a0.x + a2.x, a0.y + a2.y);
            float2 B = make_float2(a0.x - a2.x, a0.y - a2.y);
            float2 C = make_float2(a1.x + a3.x, a1.y + a3.y);
            float2 D = make_float2(a1.x - a3.x, a1.y - a3.y);

            float2 y0 = make_float2(A.x + C.x, A.y + C.y);
            float2 y1 = make_float2(B.x + sg * D.y, B.y - sg * D.x);
            float2 y2 = make_float2(A.x - C.x, A.y - C.y);
            float2 y3 = make_float2(B.x - sg * D.y, B.y + sg * D.x);

            const float2* t3 = g_tw3 + (size_t)(OFF[st] + k) * 3;
            float2 w1 = t3[0], w2 = t3[1], w3 = t3[2];
            if (DIR > 0) { w1.y = -w1.y; w2.y = -w2.y; w3.y = -w3.y; }

            s[SP(base)]         = y0;
            s[SP(base + Q)]     = cmul(y1, w1);
            s[SP(base + 2 * Q)] = cmul(y2, w2);
            s[SP(base + 3 * Q)] = cmul(y3, w3);
        }
        __syncthreads();
    }

    {
        const float CS[10] = { 1.f,  0.92387953f,  0.70710678f,  0.38268343f,  0.f,
                              -0.38268343f, -0.70710678f, -0.92387953f, -1.f, -0.92387953f};
        const float SN[10] = { 0.f, -0.38268343f, -0.70710678f, -0.92387953f, -1.f,
                              -0.92387953f, -0.70710678f, -0.38268343f,  0.f,  0.38268343f};
        float2 v[16];
        const int e0 = 16 * tid;
        #pragma unroll
        for (int m = 0; m < 16; ++m) v[m] = s[SP(e0 + m)];

        #pragma unroll
        for (int m = 0; m < 4; ++m) {
            float2 p = v[m], q = v[m + 4], r = v[m + 8], w = v[m + 12];
            float2 A = make_float2(p.x + r.x, p.y + r.y);
            float2 B = make_float2(p.x - r.x, p.y - r.y);
            float2 C = make_float2(q.x + w.x, q.y + w.y);
            float2 D = make_float2(q.x - w.x, q.y - w.y);
            float2 y0 = make_float2(A.x + C.x, A.y + C.y);
            float2 y1 = make_float2(B.x + sg * D.y, B.y - sg * D.x);
            float2 y2 = make_float2(A.x - C.x, A.y - C.y);
            float2 y3 = make_float2(B.x - sg * D.y, B.y + sg * D.x);
            float2 w1 = make_float2(CS[m],     sg * SN[m]);
            float2 w2 = make_float2(CS[2 * m], sg * SN[2 * m]);
            float2 w3 = make_float2(CS[3 * m], sg * SN[3 * m]);
            v[m]      = y0;
            v[m + 4]  = cmul(y1, w1);
            v[m + 8]  = cmul(y2, w2);
            v[m + 12] = cmul(y3, w3);
        }
        #pragma unroll
        for (int h = 0; h < 4; ++h) {
            float2 p = v[4*h], q = v[4*h+1], r = v[4*h+2], w = v[4*h+3];
            float2 A = make_float2(p.x + r.x, p.y + r.y);
            float2 B = make_float2(p.x - r.x, p.y - r.y);
            float2 C = make_float2(q.x + w.x, q.y + w.y);
            float2 D = make_float2(q.x - w.x, q.y - w.y);
            v[4*h]   = make_float2(A.x + C.x, A.y + C.y);
            v[4*h+1] = make_float2(B.x + sg * D.y, B.y - sg * D.x);
            v[4*h+2] = make_float2(A.x - C.x, A.y - C.y);
            v[4*h+3] = make_float2(B.x - sg * D.y, B.y + sg * D.x);
        }
        #pragma unroll
        for (int m = 0; m < 16; ++m) s[SP(e0 + m)] = v[m];
    }
    __syncthreads();
}

// ---------------------------------------------------------------------------
// Kernel 1: two-for-one forward FFT + PHAT whitening. 64 blocks.
// ---------------------------------------------------------------------------
__global__ void __launch_bounds__(256) k_fft_whiten(const float* __restrict__ sig)
{
    __shared__ float2 s[SMEM_PAD];
    const int tid = threadIdx.x;
    const int b  = blockIdx.x >> 2;
    const int mp = blockIdx.x & 3;
    const float* x0 = sig + (size_t)(b * NMICS + 2 * mp) * N_FFT;
    const float* x1 = x0 + N_FFT;

    for (int i = tid; i < N_FFT; i += 256)
        s[SP(i)] = make_float2(x0[i], x1[i]);
    __syncthreads();

    fft4096_dif<-1>(s, tid);

    float2* w0 = g_W + (size_t)(b * NMICS + 2 * mp) * NBINS;
    float2* w1 = w0 + NBINS;
    for (int k = tid; k < NBINS; k += 256) {
        float2 Zk = s[SP(dr12(k))];
        float2 Zn = s[SP(dr12((N_FFT - k) & (N_FFT - 1)))];
        float2 A = make_float2(Zk.x + Zn.x, Zk.y - Zn.y);
        float2 B = make_float2(Zk.y + Zn.y, Zn.x - Zk.x);
        float ia = rsqrtf(A.x * A.x + A.y * A.y + 1e-24f);
        float ib = rsqrtf(B.x * B.x + B.y * B.y + 1e-24f);
        w0[k] = make_float2(A.x * ia, A.y * ia);
        w1[k] = make_float2(B.x * ib, B.y * ib);
    }
}

// ---------------------------------------------------------------------------
// Kernel 2: cross-spectrum + inverse DIF FFT, two pairs per iFFT. 224 blocks.
// ---------------------------------------------------------------------------
__global__ void __launch_bounds__(256) k_xcorr(const int* __restrict__ comb)
{
    __shared__ float2 s[SMEM_PAD];
    const int tid = threadIdx.x;
    const int q0 = blockIdx.x * 2, q1 = q0 + 1;
    const int b0 = q0 / NPAIR, p0 = q0 % NPAIR;
    const int b1 = q1 / NPAIR, p1 = q1 % NPAIR;

    const float2* Wa0 = g_W + (size_t)(b0 * NMICS + comb[2 * p0    ]) * NBINS;
    const float2* Wb0 = g_W + (size_t)(b0 * NMICS + comb[2 * p0 + 1]) * NBINS;
    const float2* Wa1 = g_W + (size_t)(b1 * NMICS + comb[2 * p1    ]) * NBINS;
    const float2* Wb1 = g_W + (size_t)(b1 * NMICS + comb[2 * p1 + 1]) * NBINS;

    for (int k = tid; k <= N_FFT / 2; k += 256) {
        float2 a0 = Wa0[k], c0 = Wb0[k];
        float x1r = a0.x * c0.x + a0.y * c0.y;
        float x1i = a0.y * c0.x - a0.x * c0.y;
        float2 a1 = Wa1[k], c1 = Wb1[k];
        float x2r = a1.x * c1.x + a1.y * c1.y;
        float x2i = a1.y * c1.x - a1.x * c1.y;

        s[SP(k)] = make_float2(x1r - x2i, x1i + x2r);
        if (k > 0 && k < N_FFT / 2)
            s[SP(N_FFT - k)] = make_float2(x1r + x2i, x2r - x1i);
    }
    __syncthreads();

    fft4096_dif<1>(s, tid);

    for (int t = tid; t < NLAG; t += 256) {
        int idx = (t + (N_FFT - 40)) & (N_FFT - 1);
        float2 v = s[SP(dr12(idx))];
        g_cc[(p0 * NLAG + t) * BATCH + b0] = v.x;
        g_cc[(p1 * NLAG + t) * BATCH + b1] = v.y;
    }
}

// ---------------------------------------------------------------------------
// Kernel 3: SRP + argmax + final decode (fused). 148 persistent blocks,
// 1024 threads, cc table staged in dynamic smem (rows padded 8->9 float2).
// ---------------------------------------------------------------------------
#define CC_ROWS   (NPAIR * NLAG)          // 2268
#define CC_STRIDE 9                        // float2 per row (pad)
#define SRP_SMEM  (CC_ROWS * CC_STRIDE * sizeof(float2))   // 163,296 B

__device__ __forceinline__ unsigned int fkey(float f)
{
    unsigned int b = __float_as_uint(f);
    return (b & 0x80000000u) ? ~b : (b | 0x80000000u);
}

__global__ void __launch_bounds__(SRP_THREADS) k_srp(const int* __restrict__ tau, int G,
                                                     const float* __restrict__ grid_x,
                                                     const float* __restrict__ cen,
                                                     float* __restrict__ out)
{
    extern __shared__ float2 scc[];
    __shared__ unsigned long long sbest[BATCH];
    __shared__ int s_last;

    const int tid = threadIdx.x;
    if (tid < BATCH) sbest[tid] = 0ull;
    if (tid == 0) s_last = 0;

    // stage cc table: g_cc rows of 8 float2 -> smem rows of 9 float2
    const float2* gcc2 = (const float2*)g_cc;
    for (int idx = tid; idx < CC_ROWS * 8; idx += SRP_THREADS) {
        int row = idx >> 3, c = idx & 7;
        scc[row * CC_STRIDE + c] = gcc2[idx];
    }
    __syncthreads();

    const int Gpb   = (G + SRP_BLOCKS - 1) / SRP_BLOCKS;
    const int g0blk = blockIdx.x * Gpb;
    const int bp    = tid & 7;               // batches 2bp, 2bp+1
    const int gloc  = tid >> 3;              // 0..127

    for (int it = 0; it * 128 < Gpb; ++it) {
        const int lg = it * 128 + gloc;
        const int g  = g0blk + lg;
        unsigned long long k0 = 0ull, k1 = 0ull;

        if (lg < Gpb && g < G) {
            float2 pw = make_float2(0.0f, 0.0f);
            const int4* trow = (const int4*)(tau + (size_t)g * NPAIR);
            #pragma unroll
            for (int pc = 0; pc < NPAIR / 4; ++pc) {
                int4 tv = trow[pc];
                int ts[4] = { tv.x, tv.y, tv.z, tv.w };
                #pragma unroll
                for (int e = 0; e < 4; ++e) {
                    int p = pc * 4 + e;
                    float2 r = scc[(p * NLAG + ts[e]) * CC_STRIDE + bp];
                    pw.x += r.x; pw.y += r.y;
                }
            }
            const unsigned int gk = ~(unsigned int)g;
            k0 = ((unsigned long long)fkey(pw.x) << 32) | gk;
            k1 = ((unsigned long long)fkey(pw.y) << 32) | gk;
        }

        #pragma unroll
        for (int off = 8; off < 32; off <<= 1) {
            unsigned long long o0 = __shfl_xor_sync(0xFFFFFFFFu, k0, off);
            unsigned long long o1 = __shfl_xor_sync(0xFFFFFFFFu, k1, off);
            if (o0 > k0) k0 = o0;
            if (o1 > k1) k1 = o1;
        }
        if ((tid & 31) < 8) {
            if (k0) atomicMax(&sbest[bp * 2],     k0);
            if (k1) atomicMax(&sbest[bp * 2 + 1], k1);
        }
    }
    __syncthreads();

    if (tid < BATCH) atomicMax(&g_best[tid], sbest[tid]);

    // last-block-done: decode argmax and write output
    __threadfence();
    __syncthreads();
    if (tid == 0) {
        int ticket = atomicAdd(&g_done, 1);
        if (ticket == gridDim.x - 1) { __threadfence(); s_last = 1; }
    }
    __syncthreads();
    if (s_last && tid < BATCH) {
        unsigned int idx = ~(unsigned int)(g_best[tid] & 0xFFFFFFFFull);
        #pragma unroll
        for (int j = 0; j < 3; ++j)
            out[tid * 3 + j] = grid_x[(size_t)idx * 3 + j] - cen[j];
    }
}

// ---------------------------------------------------------------------------
extern "C" void kernel_launch(void* const* d_in, const int* in_sizes, int n_in,
                              void* d_out, int out_size)
{
    const float* signal = (const float*)d_in[0];
    const float* grid_x = (const float*)d_in[1];
    const int*   tau    = (const int*)d_in[2];
    const int*   comb   = (const int*)d_in[3];
    const float* cen    = (const float*)d_in[4];

    const int G = in_sizes[1] / 3;

    static bool attr_set = false;
    if (!attr_set) {
        cudaFuncSetAttribute(k_srp, cudaFuncAttributeMaxDynamicSharedMemorySize,
                             (int)SRP_SMEM);
        attr_set = true;
    }

    k_init<<<6, 256>>>();
    k_fft_whiten<<<BATCH * NMICS / 2, 256>>>(signal);
    k_xcorr<<<BATCH * NPAIR / 2, 256>>>(comb);
    k_srp<<<SRP_BLOCKS, SRP_THREADS, SRP_SMEM>>>(tau, G, grid_x, cen, (float*)d_out);
}

// round 6
// speedup vs baseline: 1.2150x; 1.2150x over previous
#include <cuda_runtime.h>
#include <stdint.h>

#define N_FFT  4096
#define NBINS  2049
#define NMICS  8
#define BATCH  16
#define NPAIR  28
#define NLAG   81
#define FFT_THREADS 512

// padded smem index: conflict-free for all FFT access patterns used here
#define SP(i) ((i) + ((i) >> 4) + ((i) >> 8))
#define SMEM_PAD 4368

__device__ float2 g_W[BATCH * NMICS * NBINS];        // whitened spectra (natural order)
__device__ float  g_cc[NPAIR * NLAG * BATCH];        // cc table [p][t][b16]
__device__ unsigned long long g_best[BATCH];
__device__ int    g_done;
__device__ float2 g_tw3[1360 * 3];                   // stage twiddles (W,W^2,W^3)

// base-4 digit reversal of 12-bit index (involution)
__device__ __forceinline__ int dr12(int i)
{
    unsigned x = __brev((unsigned)i) >> 20;
    return (int)(((x & 0xAAAu) >> 1) | ((x & 0x555u) << 1));
}

__device__ __forceinline__ float2 cmul(float2 a, float2 b)
{
    return make_float2(a.x * b.x - a.y * b.y, a.x * b.y + a.y * b.x);
}

// ---------------------------------------------------------------------------
// init: twiddle tables + reset argmax/ticket state.
// ---------------------------------------------------------------------------
__global__ void k_init()
{
    int gid = blockIdx.x * 256 + threadIdx.x;
    if (gid == 0) {
        g_done = 0;
        #pragma unroll
        for (int b = 0; b < BATCH; ++b) g_best[b] = 0ull;
    }
    if (gid < 1360) {
        int Q, k;
        if      (gid < 1024) { Q = 1024; k = gid; }
        else if (gid < 1280) { Q = 256;  k = gid - 1024; }
        else if (gid < 1344) { Q = 64;   k = gid - 1280; }
        else                 { Q = 16;   k = gid - 1344; }
        float th = -3.14159265358979323846f * (float)k / (2.0f * (float)Q);
        #pragma unroll
        for (int m = 1; m <= 3; ++m) {
            float sn, cs;
            sincosf(th * (float)m, &sn, &cs);
            g_tw3[gid * 3 + (m - 1)] = make_float2(cs, sn);
        }
    }
}

// ---------------------------------------------------------------------------
// In-place 4096-pt radix-4 DIF FFT (padded smem). Natural input, digit-
// reversed output. 4 table stages (512 thr x 2 bf) + radix-16 tail (thr 0-255).
// ---------------------------------------------------------------------------
template<int DIR>
__device__ __forceinline__ void fft4096_dif(float2* s, int tid)
{
    const float sg = (DIR < 0) ? 1.0f : -1.0f;

    const int OFF[4] = {0, 1024, 1280, 1344};
    #pragma unroll
    for (int st = 0; st < 4; ++st) {
        const int lg = 10 - 2 * st;
        const int Q  = 1 << lg;
        #pragma unroll
        for (int u = 0; u < 2; ++u) {
            int j    = tid + u * FFT_THREADS;
            int k    = j & (Q - 1);
            int base = ((j >> lg) << (lg + 2)) + k;

            float2 a0 = s[SP(base)];
            float2 a1 = s[SP(base + Q)];
            float2 a2 = s[SP(base + 2 * Q)];
            float2 a3 = s[SP(base + 3 * Q)];

            float2 A = make_float2(a0.x + a2.x, a0.y + a2.y);
            float2 B = make_float2(a0.x - a2.x, a0.y - a2.y);
            float2 C = make_float2(a1.x + a3.x, a1.y + a3.y);
            float2 D = make_float2(a1.x - a3.x, a1.y - a3.y);

            float2 y0 = make_float2(A.x + C.x, A.y + C.y);
            float2 y1 = make_float2(B.x + sg * D.y, B.y - sg * D.x);
            float2 y2 = make_float2(A.x - C.x, A.y - C.y);
            float2 y3 = make_float2(B.x - sg * D.y, B.y + sg * D.x);

            const float2* t3 = g_tw3 + (size_t)(OFF[st] + k) * 3;
            float2 w1 = t3[0], w2 = t3[1], w3 = t3[2];
            if (DIR > 0) { w1.y = -w1.y; w2.y = -w2.y; w3.y = -w3.y; }

            s[SP(base)]         = y0;
            s[SP(base + Q)]     = cmul(y1, w1);
            s[SP(base + 2 * Q)] = cmul(y2, w2);
            s[SP(base + 3 * Q)] = cmul(y3, w3);
        }
        __syncthreads();
    }

    if (tid < 256) {
        const float CS[10] = { 1.f,  0.92387953f,  0.70710678f,  0.38268343f,  0.f,
                              -0.38268343f, -0.70710678f, -0.92387953f, -1.f, -0.92387953f};
        const float SN[10] = { 0.f, -0.38268343f, -0.70710678f, -0.92387953f, -1.f,
                              -0.92387953f, -0.70710678f, -0.38268343f,  0.f,  0.38268343f};
        float2 v[16];
        const int e0 = 16 * tid;
        #pragma unroll
        for (int m = 0; m < 16; ++m) v[m] = s[SP(e0 + m)];

        #pragma unroll
        for (int m = 0; m < 4; ++m) {
            float2 p = v[m], q = v[m + 4], r = v[m + 8], w = v[m + 12];
            float2 A = make_float2(p.x + r.x, p.y + r.y);
            float2 B = make_float2(p.x - r.x, p.y - r.y);
            float2 C = make_float2(q.x + w.x, q.y + w.y);
            float2 D = make_float2(q.x - w.x, q.y - w.y);
            float2 y0 = make_float2(A.x + C.x, A.y + C.y);
            float2 y1 = make_float2(B.x + sg * D.y, B.y - sg * D.x);
            float2 y2 = make_float2(A.x - C.x, A.y - C.y);
            float2 y3 = make_float2(B.x - sg * D.y, B.y + sg * D.x);
            float2 w1 = make_float2(CS[m],     sg * SN[m]);
            float2 w2 = make_float2(CS[2 * m], sg * SN[2 * m]);
            float2 w3 = make_float2(CS[3 * m], sg * SN[3 * m]);
            v[m]      = y0;
            v[m + 4]  = cmul(y1, w1);
            v[m + 8]  = cmul(y2, w2);
            v[m + 12] = cmul(y3, w3);
        }
        #pragma unroll
        for (int h = 0; h < 4; ++h) {
            float2 p = v[4*h], q = v[4*h+1], r = v[4*h+2], w = v[4*h+3];
            float2 A = make_float2(p.x + r.x, p.y + r.y);
            float2 B = make_float2(p.x - r.x, p.y - r.y);
            float2 C = make_float2(q.x + w.x, q.y + w.y);
            float2 D = make_float2(q.x - w.x, q.y - w.y);
            v[4*h]   = make_float2(A.x + C.x, A.y + C.y);
            v[4*h+1] = make_float2(B.x + sg * D.y, B.y - sg * D.x);
            v[4*h+2] = make_float2(A.x - C.x, A.y - C.y);
            v[4*h+3] = make_float2(B.x - sg * D.y, B.y + sg * D.x);
        }
        #pragma unroll
        for (int m = 0; m < 16; ++m) s[SP(e0 + m)] = v[m];
    }
    __syncthreads();
}

// ---------------------------------------------------------------------------
// Kernel 1: two-for-one forward FFT + PHAT whitening. 64 blocks x 512 thr.
// ---------------------------------------------------------------------------
__global__ void __launch_bounds__(FFT_THREADS) k_fft_whiten(const float* __restrict__ sig)
{
    __shared__ float2 s[SMEM_PAD];
    const int tid = threadIdx.x;
    const int b  = blockIdx.x >> 2;
    const int mp = blockIdx.x & 3;
    const float* x0 = sig + (size_t)(b * NMICS + 2 * mp) * N_FFT;
    const float* x1 = x0 + N_FFT;

    for (int i = tid; i < N_FFT; i += FFT_THREADS)
        s[SP(i)] = make_float2(x0[i], x1[i]);
    __syncthreads();

    fft4096_dif<-1>(s, tid);

    float2* w0 = g_W + (size_t)(b * NMICS + 2 * mp) * NBINS;
    float2* w1 = w0 + NBINS;
    for (int k = tid; k < NBINS; k += FFT_THREADS) {
        float2 Zk = s[SP(dr12(k))];
        float2 Zn = s[SP(dr12((N_FFT - k) & (N_FFT - 1)))];
        float2 A = make_float2(Zk.x + Zn.x, Zk.y - Zn.y);
        float2 B = make_float2(Zk.y + Zn.y, Zn.x - Zk.x);
        float ia = rsqrtf(A.x * A.x + A.y * A.y + 1e-24f);
        float ib = rsqrtf(B.x * B.x + B.y * B.y + 1e-24f);
        w0[k] = make_float2(A.x * ia, A.y * ia);
        w1[k] = make_float2(B.x * ib, B.y * ib);
    }
}

// ---------------------------------------------------------------------------
// Kernel 2: cross-spectrum + inverse DIF FFT, two pairs per iFFT.
// 224 blocks x 512 thr.
// ---------------------------------------------------------------------------
__global__ void __launch_bounds__(FFT_THREADS) k_xcorr(const int* __restrict__ comb)
{
    __shared__ float2 s[SMEM_PAD];
    const int tid = threadIdx.x;
    const int q0 = blockIdx.x * 2, q1 = q0 + 1;
    const int b0 = q0 / NPAIR, p0 = q0 % NPAIR;
    const int b1 = q1 / NPAIR, p1 = q1 % NPAIR;

    const float2* Wa0 = g_W + (size_t)(b0 * NMICS + comb[2 * p0    ]) * NBINS;
    const float2* Wb0 = g_W + (size_t)(b0 * NMICS + comb[2 * p0 + 1]) * NBINS;
    const float2* Wa1 = g_W + (size_t)(b1 * NMICS + comb[2 * p1    ]) * NBINS;
    const float2* Wb1 = g_W + (size_t)(b1 * NMICS + comb[2 * p1 + 1]) * NBINS;

    for (int k = tid; k <= N_FFT / 2; k += FFT_THREADS) {
        float2 a0 = Wa0[k], c0 = Wb0[k];
        float x1r = a0.x * c0.x + a0.y * c0.y;
        float x1i = a0.y * c0.x - a0.x * c0.y;
        float2 a1 = Wa1[k], c1 = Wb1[k];
        float x2r = a1.x * c1.x + a1.y * c1.y;
        float x2i = a1.y * c1.x - a1.x * c1.y;

        s[SP(k)] = make_float2(x1r - x2i, x1i + x2r);
        if (k > 0 && k < N_FFT / 2)
            s[SP(N_FFT - k)] = make_float2(x1r + x2i, x2r - x1i);
    }
    __syncthreads();

    fft4096_dif<1>(s, tid);

    if (tid < NLAG) {
        int idx = (tid + (N_FFT - 40)) & (N_FFT - 1);
        float2 v = s[SP(dr12(idx))];
        g_cc[(p0 * NLAG + tid) * BATCH + b0] = v.x;
        g_cc[(p1 * NLAG + tid) * BATCH + b1] = v.y;
    }
}

// ---------------------------------------------------------------------------
// Kernel 3: SRP accumulation + argmax + fused final decode.
// Round-4 gather structure: 8 threads/grid point, L1 gathers (982+ blocks).
// ---------------------------------------------------------------------------
__device__ __forceinline__ unsigned int fkey(float f)
{
    unsigned int b = __float_as_uint(f);
    return (b & 0x80000000u) ? ~b : (b | 0x80000000u);
}

__global__ void __launch_bounds__(256) k_srp(const int* __restrict__ tau, int G,
                                             const float* __restrict__ grid_x,
                                             const float* __restrict__ cen,
                                             float* __restrict__ out)
{
    __shared__ unsigned long long sbest[BATCH];
    __shared__ int s_last;
    const int tid = threadIdx.x;
    if (tid < BATCH) sbest[tid] = 0ull;
    if (tid == 0) s_last = 0;
    __syncthreads();

    const int tIdx = blockIdx.x * 256 + tid;
    const int g    = tIdx >> 3;
    const int bp   = tid & 7;               // batches 2bp, 2bp+1

    unsigned long long k0 = 0ull, k1 = 0ull;

    if (g < G) {
        float2 pw = make_float2(0.0f, 0.0f);
        const int4* trow = (const int4*)(tau + (size_t)g * NPAIR);
        #pragma unroll
        for (int pc = 0; pc < NPAIR / 4; ++pc) {
            int4 tv = trow[pc];
            int ts[4] = { tv.x, tv.y, tv.z, tv.w };
            #pragma unroll
            for (int e = 0; e < 4; ++e) {
                int p = pc * 4 + e;
                float2 r = *(const float2*)(g_cc + (p * NLAG + ts[e]) * BATCH + bp * 2);
                pw.x += r.x; pw.y += r.y;
            }
        }
        const unsigned int gk = ~(unsigned int)g;
        k0 = ((unsigned long long)fkey(pw.x) << 32) | gk;
        k1 = ((unsigned long long)fkey(pw.y) << 32) | gk;
    }

    #pragma unroll
    for (int off = 8; off < 32; off <<= 1) {
        unsigned long long o0 = __shfl_xor_sync(0xFFFFFFFFu, k0, off);
        unsigned long long o1 = __shfl_xor_sync(0xFFFFFFFFu, k1, off);
        if (o0 > k0) k0 = o0;
        if (o1 > k1) k1 = o1;
    }
    if ((tid & 31) < 8) {
        atomicMax(&sbest[bp * 2],     k0);
        atomicMax(&sbest[bp * 2 + 1], k1);
    }
    __syncthreads();

    if (tid < BATCH) atomicMax(&g_best[tid], sbest[tid]);

    // last-block-done: decode argmax and write output
    __threadfence();
    __syncthreads();
    if (tid == 0) {
        int ticket = atomicAdd(&g_done, 1);
        if (ticket == (int)gridDim.x - 1) { __threadfence(); s_last = 1; }
    }
    __syncthreads();
    if (s_last && tid < BATCH) {
        unsigned int idx = ~(unsigned int)(g_best[tid] & 0xFFFFFFFFull);
        #pragma unroll
        for (int j = 0; j < 3; ++j)
            out[tid * 3 + j] = grid_x[(size_t)idx * 3 + j] - cen[j];
    }
}

// ---------------------------------------------------------------------------
extern "C" void kernel_launch(void* const* d_in, const int* in_sizes, int n_in,
                              void* d_out, int out_size)
{
    const float* signal = (const float*)d_in[0];
    const float* grid_x = (const float*)d_in[1];
    const int*   tau    = (const int*)d_in[2];
    const int*   comb   = (const int*)d_in[3];
    const float* cen    = (const float*)d_in[4];

    const int G = in_sizes[1] / 3;

    k_init<<<6, 256>>>();
    k_fft_whiten<<<BATCH * NMICS / 2, FFT_THREADS>>>(signal);
    k_xcorr<<<BATCH * NPAIR / 2, FFT_THREADS>>>(comb);
    k_srp<<<(8 * G + 255) / 256, 256>>>(tau, G, grid_x, cen, (float*)d_out);
}

// round 7
// speedup vs baseline: 1.3282x; 1.0932x over previous
#include <cuda_runtime.h>
#include <stdint.h>

#define N_FFT  4096
#define NBINS  2049
#define NMICS  8
#define BATCH  16
#define NPAIR  28
#define NLAG   81
#define FFT_THREADS 512

// padded smem index: conflict-free for all FFT access patterns used here
#define SP(i) ((i) + ((i) >> 4) + ((i) >> 8))
#define SMEM_PAD   4368
#define NTW        1360                    // twiddle entries (Q=1024,256,64,16)
#define FFT_SMEM   ((SMEM_PAD + 3 * NTW) * sizeof(float2))   // ~67.6 KB

__device__ float2 g_W[BATCH * NMICS * NBINS];        // whitened spectra (natural order)
__device__ float  g_cc[NPAIR * NLAG * BATCH];        // cc table [p][t][b16]
__device__ unsigned long long g_best[BATCH];
__device__ int    g_done;

// base-4 digit reversal of 12-bit index (involution)
__device__ __forceinline__ int dr12(int i)
{
    unsigned x = __brev((unsigned)i) >> 20;
    return (int)(((x & 0xAAAu) >> 1) | ((x & 0x555u) << 1));
}

__device__ __forceinline__ float2 cmul(float2 a, float2 b)
{
    return make_float2(a.x * b.x - a.y * b.y, a.x * b.y + a.y * b.x);
}

// ---------------------------------------------------------------------------
// Per-block twiddle generation into smem: W, W^2, W^3 for stages Q=1024..16.
// layout: tw1[NTW], tw2[NTW], tw3[NTW] (separate arrays, clean LDS.64).
// ---------------------------------------------------------------------------
__device__ __forceinline__ void gen_twiddles(float2* tw, int tid)
{
    for (int gid = tid; gid < NTW; gid += FFT_THREADS) {
        int Q, k;
        if      (gid < 1024) { Q = 1024; k = gid; }
        else if (gid < 1280) { Q = 256;  k = gid - 1024; }
        else if (gid < 1344) { Q = 64;   k = gid - 1280; }
        else                 { Q = 16;   k = gid - 1344; }
        float th = -3.14159265358979323846f * (float)k / (2.0f * (float)Q);
        float s1, c1, s2, c2, s3, c3;
        __sincosf(th,        &s1, &c1);
        __sincosf(th * 2.0f, &s2, &c2);
        __sincosf(th * 3.0f, &s3, &c3);
        tw[gid]           = make_float2(c1, s1);
        tw[gid + NTW]     = make_float2(c2, s2);
        tw[gid + 2 * NTW] = make_float2(c3, s3);
    }
}

// ---------------------------------------------------------------------------
// In-place 4096-pt radix-4 DIF FFT (padded smem). Natural input, digit-
// reversed output. 4 smem-twiddle stages (512 thr x 2 bf) + radix-16 tail.
// ---------------------------------------------------------------------------
template<int DIR>
__device__ __forceinline__ void fft4096_dif(float2* s, const float2* tw, int tid)
{
    const float sg = (DIR < 0) ? 1.0f : -1.0f;

    const int OFF[4] = {0, 1024, 1280, 1344};
    #pragma unroll
    for (int st = 0; st < 4; ++st) {
        const int lg = 10 - 2 * st;
        const int Q  = 1 << lg;
        #pragma unroll
        for (int u = 0; u < 2; ++u) {
            int j    = tid + u * FFT_THREADS;
            int k    = j & (Q - 1);
            int base = ((j >> lg) << (lg + 2)) + k;

            float2 a0 = s[SP(base)];
            float2 a1 = s[SP(base + Q)];
            float2 a2 = s[SP(base + 2 * Q)];
            float2 a3 = s[SP(base + 3 * Q)];

            float2 A = make_float2(a0.x + a2.x, a0.y + a2.y);
            float2 B = make_float2(a0.x - a2.x, a0.y - a2.y);
            float2 C = make_float2(a1.x + a3.x, a1.y + a3.y);
            float2 D = make_float2(a1.x - a3.x, a1.y - a3.y);

            float2 y0 = make_float2(A.x + C.x, A.y + C.y);
            float2 y1 = make_float2(B.x + sg * D.y, B.y - sg * D.x);
            float2 y2 = make_float2(A.x - C.x, A.y - C.y);
            float2 y3 = make_float2(B.x - sg * D.y, B.y + sg * D.x);

            int ti = OFF[st] + k;
            float2 w1 = tw[ti];
            float2 w2 = tw[ti + NTW];
            float2 w3 = tw[ti + 2 * NTW];
            if (DIR > 0) { w1.y = -w1.y; w2.y = -w2.y; w3.y = -w3.y; }

            s[SP(base)]         = y0;
            s[SP(base + Q)]     = cmul(y1, w1);
            s[SP(base + 2 * Q)] = cmul(y2, w2);
            s[SP(base + 3 * Q)] = cmul(y3, w3);
        }
        __syncthreads();
    }

    if (tid < 256) {
        const float CS[10] = { 1.f,  0.92387953f,  0.70710678f,  0.38268343f,  0.f,
                              -0.38268343f, -0.70710678f, -0.92387953f, -1.f, -0.92387953f};
        const float SN[10] = { 0.f, -0.38268343f, -0.70710678f, -0.92387953f, -1.f,
                              -0.92387953f, -0.70710678f, -0.38268343f,  0.f,  0.38268343f};
        float2 v[16];
        const int e0 = 16 * tid;
        #pragma unroll
        for (int m = 0; m < 16; ++m) v[m] = s[SP(e0 + m)];

        #pragma unroll
        for (int m = 0; m < 4; ++m) {
            float2 p = v[m], q = v[m + 4], r = v[m + 8], w = v[m + 12];
            float2 A = make_float2(p.x + r.x, p.y + r.y);
            float2 B = make_float2(p.x - r.x, p.y - r.y);
            float2 C = make_float2(q.x + w.x, q.y + w.y);
            float2 D = make_float2(q.x - w.x, q.y - w.y);
            float2 y0 = make_float2(A.x + C.x, A.y + C.y);
            float2 y1 = make_float2(B.x + sg * D.y, B.y - sg * D.x);
            float2 y2 = make_float2(A.x - C.x, A.y - C.y);
            float2 y3 = make_float2(B.x - sg * D.y, B.y + sg * D.x);
            float2 w1 = make_float2(CS[m],     sg * SN[m]);
            float2 w2 = make_float2(CS[2 * m], sg * SN[2 * m]);
            float2 w3 = make_float2(CS[3 * m], sg * SN[3 * m]);
            v[m]      = y0;
            v[m + 4]  = cmul(y1, w1);
            v[m + 8]  = cmul(y2, w2);
            v[m + 12] = cmul(y3, w3);
        }
        #pragma unroll
        for (int h = 0; h < 4; ++h) {
            float2 p = v[4*h], q = v[4*h+1], r = v[4*h+2], w = v[4*h+3];
            float2 A = make_float2(p.x + r.x, p.y + r.y);
            float2 B = make_float2(p.x - r.x, p.y - r.y);
            float2 C = make_float2(q.x + w.x, q.y + w.y);
            float2 D = make_float2(q.x - w.x, q.y - w.y);
            v[4*h]   = make_float2(A.x + C.x, A.y + C.y);
            v[4*h+1] = make_float2(B.x + sg * D.y, B.y - sg * D.x);
            v[4*h+2] = make_float2(A.x - C.x, A.y - C.y);
            v[4*h+3] = make_float2(B.x - sg * D.y, B.y + sg * D.x);
        }
        #pragma unroll
        for (int m = 0; m < 16; ++m) s[SP(e0 + m)] = v[m];
    }
    __syncthreads();
}

// ---------------------------------------------------------------------------
// Kernel 1: two-for-one forward FFT + PHAT whitening. 64 blocks x 512 thr.
// ---------------------------------------------------------------------------
__global__ void __launch_bounds__(FFT_THREADS) k_fft_whiten(const float* __restrict__ sig)
{
    extern __shared__ float2 dyn[];
    float2* s  = dyn;
    float2* tw = dyn + SMEM_PAD;

    const int tid = threadIdx.x;
    const int b  = blockIdx.x >> 2;
    const int mp = blockIdx.x & 3;
    const float* x0 = sig + (size_t)(b * NMICS + 2 * mp) * N_FFT;
    const float* x1 = x0 + N_FFT;

    gen_twiddles(tw, tid);
    for (int i = tid; i < N_FFT; i += FFT_THREADS)
        s[SP(i)] = make_float2(x0[i], x1[i]);
    __syncthreads();

    fft4096_dif<-1>(s, tw, tid);

    float2* w0 = g_W + (size_t)(b * NMICS + 2 * mp) * NBINS;
    float2* w1 = w0 + NBINS;
    for (int k = tid; k < NBINS; k += FFT_THREADS) {
        float2 Zk = s[SP(dr12(k))];
        float2 Zn = s[SP(dr12((N_FFT - k) & (N_FFT - 1)))];
        float2 A = make_float2(Zk.x + Zn.x, Zk.y - Zn.y);
        float2 B = make_float2(Zk.y + Zn.y, Zn.x - Zk.x);
        float ia = rsqrtf(A.x * A.x + A.y * A.y + 1e-24f);
        float ib = rsqrtf(B.x * B.x + B.y * B.y + 1e-24f);
        w0[k] = make_float2(A.x * ia, A.y * ia);
        w1[k] = make_float2(B.x * ib, B.y * ib);
    }
}

// ---------------------------------------------------------------------------
// Kernel 2: cross-spectrum + inverse DIF FFT, two pairs per iFFT.
// 224 blocks x 512 thr. Block 0 also resets argmax/ticket state for k_srp
// (stream-ordered before k_srp launch).
// ---------------------------------------------------------------------------
__global__ void __launch_bounds__(FFT_THREADS) k_xcorr(const int* __restrict__ comb)
{
    extern __shared__ float2 dyn[];
    float2* s  = dyn;
    float2* tw = dyn + SMEM_PAD;

    const int tid = threadIdx.x;
    if (blockIdx.x == 0 && tid == 0) {
        g_done = 0;
        #pragma unroll
        for (int b = 0; b < BATCH; ++b) g_best[b] = 0ull;
    }

    const int q0 = blockIdx.x * 2, q1 = q0 + 1;
    const int b0 = q0 / NPAIR, p0 = q0 % NPAIR;
    const int b1 = q1 / NPAIR, p1 = q1 % NPAIR;

    const float2* Wa0 = g_W + (size_t)(b0 * NMICS + comb[2 * p0    ]) * NBINS;
    const float2* Wb0 = g_W + (size_t)(b0 * NMICS + comb[2 * p0 + 1]) * NBINS;
    const float2* Wa1 = g_W + (size_t)(b1 * NMICS + comb[2 * p1    ]) * NBINS;
    const float2* Wb1 = g_W + (size_t)(b1 * NMICS + comb[2 * p1 + 1]) * NBINS;

    gen_twiddles(tw, tid);
    for (int k = tid; k <= N_FFT / 2; k += FFT_THREADS) {
        float2 a0 = Wa0[k], c0 = Wb0[k];
        float x1r = a0.x * c0.x + a0.y * c0.y;
        float x1i = a0.y * c0.x - a0.x * c0.y;
        float2 a1 = Wa1[k], c1 = Wb1[k];
        float x2r = a1.x * c1.x + a1.y * c1.y;
        float x2i = a1.y * c1.x - a1.x * c1.y;

        s[SP(k)] = make_float2(x1r - x2i, x1i + x2r);
        if (k > 0 && k < N_FFT / 2)
            s[SP(N_FFT - k)] = make_float2(x1r + x2i, x2r - x1i);
    }
    __syncthreads();

    fft4096_dif<1>(s, tw, tid);

    if (tid < NLAG) {
        int idx = (tid + (N_FFT - 40)) & (N_FFT - 1);
        float2 v = s[SP(dr12(idx))];
        g_cc[(p0 * NLAG + tid) * BATCH + b0] = v.x;
        g_cc[(p1 * NLAG + tid) * BATCH + b1] = v.y;
    }
}

// ---------------------------------------------------------------------------
// Kernel 3: SRP accumulation + argmax + fused final decode.
// 8 threads/grid point, L1 gathers. Fence only on the 16 threads that
// publish g_best (release side) — NOT all 256 (round-6 regression fix).
// ---------------------------------------------------------------------------
__device__ __forceinline__ unsigned int fkey(float f)
{
    unsigned int b = __float_as_uint(f);
    return (b & 0x80000000u) ? ~b : (b | 0x80000000u);
}

__global__ void __launch_bounds__(256) k_srp(const int* __restrict__ tau, int G,
                                             const float* __restrict__ grid_x,
                                             const float* __restrict__ cen,
                                             float* __restrict__ out)
{
    __shared__ unsigned long long sbest[BATCH];
    __shared__ int s_last;
    const int tid = threadIdx.x;
    if (tid < BATCH) sbest[tid] = 0ull;
    if (tid == 0) s_last = 0;
    __syncthreads();

    const int tIdx = blockIdx.x * 256 + tid;
    const int g    = tIdx >> 3;
    const int bp   = tid & 7;               // batches 2bp, 2bp+1

    unsigned long long k0 = 0ull, k1 = 0ull;

    if (g < G) {
        float2 pw = make_float2(0.0f, 0.0f);
        const int4* trow = (const int4*)(tau + (size_t)g * NPAIR);
        #pragma unroll
        for (int pc = 0; pc < NPAIR / 4; ++pc) {
            int4 tv = trow[pc];
            int ts[4] = { tv.x, tv.y, tv.z, tv.w };
            #pragma unroll
            for (int e = 0; e < 4; ++e) {
                int p = pc * 4 + e;
                float2 r = *(const float2*)(g_cc + (p * NLAG + ts[e]) * BATCH + bp * 2);
                pw.x += r.x; pw.y += r.y;
            }
        }
        const unsigned int gk = ~(unsigned int)g;
        k0 = ((unsigned long long)fkey(pw.x) << 32) | gk;
        k1 = ((unsigned long long)fkey(pw.y) << 32) | gk;
    }

    #pragma unroll
    for (int off = 8; off < 32; off <<= 1) {
        unsigned long long o0 = __shfl_xor_sync(0xFFFFFFFFu, k0, off);
        unsigned long long o1 = __shfl_xor_sync(0xFFFFFFFFu, k1, off);
        if (o0 > k0) k0 = o0;
        if (o1 > k1) k1 = o1;
    }
    if ((tid & 31) < 8) {
        atomicMax(&sbest[bp * 2],     k0);
        atomicMax(&sbest[bp * 2 + 1], k1);
    }
    __syncthreads();

    // release side: publish block result, fence ONLY in publishing threads
    if (tid < BATCH) {
        atomicMax(&g_best[tid], sbest[tid]);
        __threadfence();
    }
    __syncthreads();
    if (tid == 0) {
        int ticket = atomicAdd(&g_done, 1);
        if (ticket == (int)gridDim.x - 1) { __threadfence(); s_last = 1; }
    }
    __syncthreads();
    if (s_last && tid < BATCH) {
        unsigned long long v = atomicMax(&g_best[tid], 0ull);   // coherent read
        unsigned int idx = ~(unsigned int)(v & 0xFFFFFFFFull);
        #pragma unroll
        for (int j = 0; j < 3; ++j)
            out[tid * 3 + j] = grid_x[(size_t)idx * 3 + j] - cen[j];
    }
}

// ---------------------------------------------------------------------------
extern "C" void kernel_launch(void* const* d_in, const int* in_sizes, int n_in,
                              void* d_out, int out_size)
{
    const float* signal = (const float*)d_in[0];
    const float* grid_x = (const float*)d_in[1];
    const int*   tau    = (const int*)d_in[2];
    const int*   comb   = (const int*)d_in[3];
    const float* cen    = (const float*)d_in[4];

    const int G = in_sizes[1] / 3;

    cudaFuncSetAttribute(k_fft_whiten, cudaFuncAttributeMaxDynamicSharedMemorySize,
                         (int)FFT_SMEM);
    cudaFuncSetAttribute(k_xcorr, cudaFuncAttributeMaxDynamicSharedMemorySize,
                         (int)FFT_SMEM);

    k_fft_whiten<<<BATCH * NMICS / 2, FFT_THREADS, FFT_SMEM>>>(signal);
    k_xcorr<<<BATCH * NPAIR / 2, FFT_THREADS, FFT_SMEM>>>(comb);
    k_srp<<<(8 * G + 255) / 256, 256>>>(tau, G, grid_x, cen, (float*)d_out);
}

// round 8
// speedup vs baseline: 1.3419x; 1.0103x over previous
#include <cuda_runtime.h>
#include <stdint.h>

#define N_FFT  4096
#define NBINS  2049
#define NMICS  8
#define BATCH  16
#define NPAIR  28
#define NLAG   81
#define FFT_THREADS 512

// padded smem index: conflict-free / near-conflict-free for patterns used
#define SP(i) ((i) + ((i) >> 4) + ((i) >> 8))

// ----- 4096-pt iFFT (xcorr) constants -----
#define SMEM_PAD   4368
#define NTW        1360
#define XC_SMEM    ((SMEM_PAD + 3 * NTW) * sizeof(float2))    // ~67.6 KB

// ----- 2048-pt forward FFT (whiten) constants -----
#define N2         2048
#define SMEM_PAD2  2192                   // SP(2047)=2181 -> round up
#define NTW2       682                    // Q=512,128,32,8,2
#define WH_SMEM    ((SMEM_PAD2 + 3 * NTW2) * sizeof(float2))  // ~33.9 KB

__device__ float2 g_W[BATCH * NMICS * NBINS];        // whitened spectra (natural order)
__device__ float  g_cc[NPAIR * NLAG * BATCH];        // cc table [p][t][b16]
__device__ unsigned long long g_best[BATCH];
__device__ int    g_done;

// base-4 digit reversal of 12-bit index (involution) — 4096 iFFT output perm
__device__ __forceinline__ int dr12(int i)
{
    unsigned x = __brev((unsigned)i) >> 20;
    return (int)(((x & 0xAAAu) >> 1) | ((x & 0x555u) << 1));
}

// DIF output position for the 2048-pt chain (radix 4,4,4,4,4 then 2)
__device__ __forceinline__ int perm2048(int k)
{
    return ((k & 3) << 9) + (((k >> 2) & 3) << 7) + (((k >> 4) & 3) << 5)
         + (((k >> 6) & 3) << 3) + (((k >> 8) & 3) << 1) + (k >> 10);
}

__device__ __forceinline__ float2 cmul(float2 a, float2 b)
{
    return make_float2(a.x * b.x - a.y * b.y, a.x * b.y + a.y * b.x);
}

// ===========================================================================
// Kernel 1: forward real-4096 FFT via 2048-pt complex FFT + untangle + PHAT
// whiten. One block per (batch, mic): 128 blocks x 512 threads.
// ===========================================================================
__global__ void __launch_bounds__(FFT_THREADS) k_fft_whiten(const float* __restrict__ sig)
{
    extern __shared__ float2 dyn[];
    float2* s  = dyn;                 // SMEM_PAD2
    float2* tw = dyn + SMEM_PAD2;     // 3 * NTW2

    const int tid = threadIdx.x;

    // twiddles for stages Q=512,128,32,8,2 (forward sign)
    for (int gid = tid; gid < NTW2; gid += FFT_THREADS) {
        int Q, k;
        if      (gid < 512) { Q = 512; k = gid; }
        else if (gid < 640) { Q = 128; k = gid - 512; }
        else if (gid < 672) { Q = 32;  k = gid - 640; }
        else if (gid < 680) { Q = 8;   k = gid - 672; }
        else                { Q = 2;   k = gid - 680; }
        float th = -3.14159265358979323846f * (float)k / (2.0f * (float)Q);
        float s1, c1, s2, c2, s3, c3;
        __sincosf(th,        &s1, &c1);
        __sincosf(th * 2.0f, &s2, &c2);
        __sincosf(th * 3.0f, &s3, &c3);
        tw[gid]            = make_float2(c1, s1);
        tw[gid + NTW2]     = make_float2(c2, s2);
        tw[gid + 2 * NTW2] = make_float2(c3, s3);
    }

    // pack z[n] = x[2n] + i*x[2n+1] — contiguous float2 loads
    const float2* xz = (const float2*)(sig + (size_t)blockIdx.x * N_FFT);
    for (int n = tid; n < N2; n += FFT_THREADS)
        s[SP(n)] = xz[n];
    __syncthreads();

    // 5 radix-4 DIF stages: Q = 512,128,32,8,2  (1 butterfly/thread/stage)
    const int OFF[5] = {0, 512, 640, 672, 680};
    #pragma unroll
    for (int st = 0; st < 5; ++st) {
        const int lg = 9 - 2 * st;
        const int Q  = 1 << lg;
        int j    = tid;
        int k    = j & (Q - 1);
        int base = ((j >> lg) << (lg + 2)) + k;

        float2 a0 = s[SP(base)];
        float2 a1 = s[SP(base + Q)];
        float2 a2 = s[SP(base + 2 * Q)];
        float2 a3 = s[SP(base + 3 * Q)];

        float2 A = make_float2(a0.x + a2.x, a0.y + a2.y);
        float2 B = make_float2(a0.x - a2.x, a0.y - a2.y);
        float2 C = make_float2(a1.x + a3.x, a1.y + a3.y);
        float2 D = make_float2(a1.x - a3.x, a1.y - a3.y);

        // forward: y1 = B - i D, y3 = B + i D
        float2 y0 = make_float2(A.x + C.x, A.y + C.y);
        float2 y1 = make_float2(B.x + D.y, B.y - D.x);
        float2 y2 = make_float2(A.x - C.x, A.y - C.y);
        float2 y3 = make_float2(B.x - D.y, B.y + D.x);

        int ti = OFF[st] + k;
        s[SP(base)]         = y0;
        s[SP(base + Q)]     = cmul(y1, tw[ti]);
        s[SP(base + 2 * Q)] = cmul(y2, tw[ti + NTW2]);
        s[SP(base + 3 * Q)] = cmul(y3, tw[ti + 2 * NTW2]);
        __syncthreads();
    }

    // final radix-2 stage on adjacent pairs (no twiddle): 2 bf/thread
    #pragma unroll
    for (int u = 0; u < 2; ++u) {
        int j = tid + u * FFT_THREADS;
        float2 a = s[SP(2 * j)];
        float2 b = s[SP(2 * j + 1)];
        s[SP(2 * j)]     = make_float2(a.x + b.x, a.y + b.y);
        s[SP(2 * j + 1)] = make_float2(a.x - b.x, a.y - b.y);
    }
    __syncthreads();

    // untangle real spectrum + whiten:
    // X[k] = (Zk + conj(Z-k)) - i * e^{-i pi k/2048} * (Zk - conj(Z-k))
    float2* w = g_W + (size_t)blockIdx.x * NBINS;
    for (int k = tid; k < NBINS; k += FFT_THREADS) {
        int m  = k & (N2 - 1);
        int mc = (N2 - k) & (N2 - 1);
        float2 Zk = s[SP(perm2048(m))];
        float2 Zc = s[SP(perm2048(mc))];

        float Ax = Zk.x + Zc.x, Ay = Zk.y - Zc.y;
        float Bx = Zk.x - Zc.x, By = Zk.y + Zc.y;

        float sn, cs;
        __sincosf(-3.14159265358979323846f * (float)k / (float)N2, &sn, &cs);
        // X = A - i*(W*B);  W*B = (cs*Bx - sn*By, cs*By + sn*Bx)
        float Xx = Ax + (cs * By + sn * Bx);
        float Xy = Ay - (cs * Bx - sn * By);

        float inv = rsqrtf(Xx * Xx + Xy * Xy + 1e-24f);
        w[k] = make_float2(Xx * inv, Xy * inv);
    }
}

// ===========================================================================
// 4096-pt radix-4 DIF inverse FFT machinery (unchanged from round 7)
// ===========================================================================
__device__ __forceinline__ void gen_twiddles(float2* tw, int tid)
{
    for (int gid = tid; gid < NTW; gid += FFT_THREADS) {
        int Q, k;
        if      (gid < 1024) { Q = 1024; k = gid; }
        else if (gid < 1280) { Q = 256;  k = gid - 1024; }
        else if (gid < 1344) { Q = 64;   k = gid - 1280; }
        else                 { Q = 16;   k = gid - 1344; }
        float th = -3.14159265358979323846f * (float)k / (2.0f * (float)Q);
        float s1, c1, s2, c2, s3, c3;
        __sincosf(th,        &s1, &c1);
        __sincosf(th * 2.0f, &s2, &c2);
        __sincosf(th * 3.0f, &s3, &c3);
        tw[gid]           = make_float2(c1, s1);
        tw[gid + NTW]     = make_float2(c2, s2);
        tw[gid + 2 * NTW] = make_float2(c3, s3);
    }
}

__device__ __forceinline__ void ifft4096_dif(float2* s, const float2* tw, int tid)
{
    const int OFF[4] = {0, 1024, 1280, 1344};
    #pragma unroll
    for (int st = 0; st < 4; ++st) {
        const int lg = 10 - 2 * st;
        const int Q  = 1 << lg;
        #pragma unroll
        for (int u = 0; u < 2; ++u) {
            int j    = tid + u * FFT_THREADS;
            int k    = j & (Q - 1);
            int base = ((j >> lg) << (lg + 2)) + k;

            float2 a0 = s[SP(base)];
            float2 a1 = s[SP(base + Q)];
            float2 a2 = s[SP(base + 2 * Q)];
            float2 a3 = s[SP(base + 3 * Q)];

            float2 A = make_float2(a0.x + a2.x, a0.y + a2.y);
            float2 B = make_float2(a0.x - a2.x, a0.y - a2.y);
            float2 C = make_float2(a1.x + a3.x, a1.y + a3.y);
            float2 D = make_float2(a1.x - a3.x, a1.y - a3.y);

            // inverse: y1 = B + i D, y3 = B - i D; conj twiddles
            float2 y0 = make_float2(A.x + C.x, A.y + C.y);
            float2 y1 = make_float2(B.x - D.y, B.y + D.x);
            float2 y2 = make_float2(A.x - C.x, A.y - C.y);
            float2 y3 = make_float2(B.x + D.y, B.y - D.x);

            int ti = OFF[st] + k;
            float2 w1 = tw[ti];           w1.y = -w1.y;
            float2 w2 = tw[ti + NTW];     w2.y = -w2.y;
            float2 w3 = tw[ti + 2 * NTW]; w3.y = -w3.y;

            s[SP(base)]         = y0;
            s[SP(base + Q)]     = cmul(y1, w1);
            s[SP(base + 2 * Q)] = cmul(y2, w2);
            s[SP(base + 3 * Q)] = cmul(y3, w3);
        }
        __syncthreads();
    }

    if (tid < 256) {
        const float CS[10] = { 1.f,  0.92387953f,  0.70710678f,  0.38268343f,  0.f,
                              -0.38268343f, -0.70710678f, -0.92387953f, -1.f, -0.92387953f};
        const float SN[10] = { 0.f, -0.38268343f, -0.70710678f, -0.92387953f, -1.f,
                              -0.92387953f, -0.70710678f, -0.38268343f,  0.f,  0.38268343f};
        const float sg = -1.0f;          // inverse
        float2 v[16];
        const int e0 = 16 * tid;
        #pragma unroll
        for (int m = 0; m < 16; ++m) v[m] = s[SP(e0 + m)];

        #pragma unroll
        for (int m = 0; m < 4; ++m) {
            float2 p = v[m], q = v[m + 4], r = v[m + 8], w = v[m + 12];
            float2 A = make_float2(p.x + r.x, p.y + r.y);
            float2 B = make_float2(p.x - r.x, p.y - r.y);
            float2 C = make_float2(q.x + w.x, q.y + w.y);
            float2 D = make_float2(q.x - w.x, q.y - w.y);
            float2 y0 = make_float2(A.x + C.x, A.y + C.y);
            float2 y1 = make_float2(B.x + sg * D.y, B.y - sg * D.x);
            float2 y2 = make_float2(A.x - C.x, A.y - C.y);
            float2 y3 = make_float2(B.x - sg * D.y, B.y + sg * D.x);
            float2 w1 = make_float2(CS[m],     sg * SN[m]);
            float2 w2 = make_float2(CS[2 * m], sg * SN[2 * m]);
            float2 w3 = make_float2(CS[3 * m], sg * SN[3 * m]);
            v[m]      = y0;
            v[m + 4]  = cmul(y1, w1);
            v[m + 8]  = cmul(y2, w2);
            v[m + 12] = cmul(y3, w3);
        }
        #pragma unroll
        for (int h = 0; h < 4; ++h) {
            float2 p = v[4*h], q = v[4*h+1], r = v[4*h+2], w = v[4*h+3];
            float2 A = make_float2(p.x + r.x, p.y + r.y);
            float2 B = make_float2(p.x - r.x, p.y - r.y);
            float2 C = make_float2(q.x + w.x, q.y + w.y);
            float2 D = make_float2(q.x - w.x, q.y - w.y);
            v[4*h]   = make_float2(A.x + C.x, A.y + C.y);
            v[4*h+1] = make_float2(B.x + sg * D.y, B.y - sg * D.x);
            v[4*h+2] = make_float2(A.x - C.x, A.y - C.y);
            v[4*h+3] = make_float2(B.x - sg * D.y, B.y + sg * D.x);
        }
        #pragma unroll
        for (int m = 0; m < 16; ++m) s[SP(e0 + m)] = v[m];
    }
    __syncthreads();
}

// ===========================================================================
// Kernel 2: cross-spectrum + inverse FFT, two pairs per iFFT. 224 blocks.
// Block 0 resets argmax/ticket state (stream-ordered before k_srp).
// ===========================================================================
__global__ void __launch_bounds__(FFT_THREADS) k_xcorr(const int* __restrict__ comb)
{
    extern __shared__ float2 dyn[];
    float2* s  = dyn;
    float2* tw = dyn + SMEM_PAD;

    const int tid = threadIdx.x;
    if (blockIdx.x == 0 && tid == 0) {
        g_done = 0;
        #pragma unroll
        for (int b = 0; b < BATCH; ++b) g_best[b] = 0ull;
    }

    const int q0 = blockIdx.x * 2, q1 = q0 + 1;
    const int b0 = q0 / NPAIR, p0 = q0 % NPAIR;
    const int b1 = q1 / NPAIR, p1 = q1 % NPAIR;

    const float2* Wa0 = g_W + (size_t)(b0 * NMICS + comb[2 * p0    ]) * NBINS;
    const float2* Wb0 = g_W + (size_t)(b0 * NMICS + comb[2 * p0 + 1]) * NBINS;
    const float2* Wa1 = g_W + (size_t)(b1 * NMICS + comb[2 * p1    ]) * NBINS;
    const float2* Wb1 = g_W + (size_t)(b1 * NMICS + comb[2 * p1 + 1]) * NBINS;

    gen_twiddles(tw, tid);
    for (int k = tid; k <= N_FFT / 2; k += FFT_THREADS) {
        float2 a0 = Wa0[k], c0 = Wb0[k];
        float x1r = a0.x * c0.x + a0.y * c0.y;
        float x1i = a0.y * c0.x - a0.x * c0.y;
        float2 a1 = Wa1[k], c1 = Wb1[k];
        float x2r = a1.x * c1.x + a1.y * c1.y;
        float x2i = a1.y * c1.x - a1.x * c1.y;

        s[SP(k)] = make_float2(x1r - x2i, x1i + x2r);
        if (k > 0 && k < N_FFT / 2)
            s[SP(N_FFT - k)] = make_float2(x1r + x2i, x2r - x1i);
    }
    __syncthreads();

    ifft4096_dif(s, tw, tid);

    if (tid < NLAG) {
        int idx = (tid + (N_FFT - 40)) & (N_FFT - 1);
        float2 v = s[SP(dr12(idx))];
        g_cc[(p0 * NLAG + tid) * BATCH + b0] = v.x;
        g_cc[(p1 * NLAG + tid) * BATCH + b1] = v.y;
    }
}

// ===========================================================================
// Kernel 3: SRP accumulation + argmax + fused final decode.
// ===========================================================================
__device__ __forceinline__ unsigned int fkey(float f)
{
    unsigned int b = __float_as_uint(f);
    return (b & 0x80000000u) ? ~b : (b | 0x80000000u);
}

__global__ void __launch_bounds__(256) k_srp(const int* __restrict__ tau, int G,
                                             const float* __restrict__ grid_x,
                                             const float* __restrict__ cen,
                                             float* __restrict__ out)
{
    __shared__ unsigned long long sbest[BATCH];
    __shared__ int s_last;
    const int tid = threadIdx.x;
    if (tid < BATCH) sbest[tid] = 0ull;
    if (tid == 0) s_last = 0;
    __syncthreads();

    const int tIdx = blockIdx.x * 256 + tid;
    const int g    = tIdx >> 3;
    const int bp   = tid & 7;

    unsigned long long k0 = 0ull, k1 = 0ull;

    if (g < G) {
        float2 pw = make_float2(0.0f, 0.0f);
        const int4* trow = (const int4*)(tau + (size_t)g * NPAIR);
        #pragma unroll
        for (int pc = 0; pc < NPAIR / 4; ++pc) {
            int4 tv = trow[pc];
            int ts[4] = { tv.x, tv.y, tv.z, tv.w };
            #pragma unroll
            for (int e = 0; e < 4; ++e) {
                int p = pc * 4 + e;
                float2 r = *(const float2*)(g_cc + (p * NLAG + ts[e]) * BATCH + bp * 2);
                pw.x += r.x; pw.y += r.y;
            }
        }
        const unsigned int gk = ~(unsigned int)g;
        k0 = ((unsigned long long)fkey(pw.x) << 32) | gk;
        k1 = ((unsigned long long)fkey(pw.y) << 32) | gk;
    }

    #pragma unroll
    for (int off = 8; off < 32; off <<= 1) {
        unsigned long long o0 = __shfl_xor_sync(0xFFFFFFFFu, k0, off);
        unsigned long long o1 = __shfl_xor_sync(0xFFFFFFFFu, k1, off);
        if (o0 > k0) k0 = o0;
        if (o1 > k1) k1 = o1;
    }
    if ((tid & 31) < 8) {
        atomicMax(&sbest[bp * 2],     k0);
        atomicMax(&sbest[bp * 2 + 1], k1);
    }
    __syncthreads();

    if (tid < BATCH) {
        atomicMax(&g_best[tid], sbest[tid]);
        __threadfence();
    }
    __syncthreads();
    if (tid == 0) {
        int ticket = atomicAdd(&g_done, 1);
        if (ticket == (int)gridDim.x - 1) { __threadfence(); s_last = 1; }
    }
    __syncthreads();
    if (s_last && tid < BATCH) {
        unsigned long long v = atomicMax(&g_best[tid], 0ull);
        unsigned int idx = ~(unsigned int)(v & 0xFFFFFFFFull);
        #pragma unroll
        for (int j = 0; j < 3; ++j)
            out[tid * 3 + j] = grid_x[(size_t)idx * 3 + j] - cen[j];
    }
}

// ---------------------------------------------------------------------------
extern "C" void kernel_launch(void* const* d_in, const int* in_sizes, int n_in,
                              void* d_out, int out_size)
{
    const float* signal = (const float*)d_in[0];
    const float* grid_x = (const float*)d_in[1];
    const int*   tau    = (const int*)d_in[2];
    const int*   comb   = (const int*)d_in[3];
    const float* cen    = (const float*)d_in[4];

    const int G = in_sizes[1] / 3;

    cudaFuncSetAttribute(k_fft_whiten, cudaFuncAttributeMaxDynamicSharedMemorySize,
                         (int)WH_SMEM);
    cudaFuncSetAttribute(k_xcorr, cudaFuncAttributeMaxDynamicSharedMemorySize,
                         (int)XC_SMEM);

    k_fft_whiten<<<BATCH * NMICS, FFT_THREADS, WH_SMEM>>>(signal);
    k_xcorr<<<BATCH * NPAIR / 2, FFT_THREADS, XC_SMEM>>>(comb);
    k_srp<<<(8 * G + 255) / 256, 256>>>(tau, G, grid_x, cen, (float*)d_out);
}